// round 9
// baseline (speedup 1.0000x reference)
#include <cuda_runtime.h>
#include <cstdint>

#define T_STEPS 512

// Scratch (allocation-free rule: __device__ globals)
// proj[bucket][lane] = (Pi*0.5, Pf*0.5, Pc*1.0, Po*0.5)  (0.5 = sigmoid-via-tanh prescale)
__device__ __align__(16) float g_proj2[4096 * 32 * 4];
// Rpack: ull at ((c*16 + j)*32 + lane) = (R[2j][col]*s_c, R[2j+1][col]*s_c), col = c*32+lane
__device__ __align__(16) unsigned long long g_R[4 * 16 * 32];

// ---------- packed f32x2 helpers ----------
__device__ __forceinline__ void fma2(unsigned long long& acc, unsigned long long a, unsigned long long b) {
    asm("fma.rn.f32x2 %0, %1, %2, %0;" : "+l"(acc) : "l"(a), "l"(b));
}
__device__ __forceinline__ void add2(unsigned long long& acc, unsigned long long a) {
    asm("add.rn.f32x2 %0, %0, %1;" : "+l"(acc) : "l"(a));
}
__device__ __forceinline__ unsigned long long pk2(float lo, float hi) {
    unsigned long long r;
    asm("mov.b64 %0, {%1, %2};" : "=l"(r) : "f"(lo), "f"(hi));
    return r;
}
__device__ __forceinline__ void unpk2(unsigned long long v, float& lo, float& hi) {
    asm("mov.b64 {%0, %1}, %2;" : "=f"(lo), "=f"(hi) : "l"(v));
}
__device__ __forceinline__ float ftanh(float x) {
    float y; asm("tanh.approx.f32 %0, %1;" : "=f"(y) : "f"(x)); return y;
}
__device__ __forceinline__ float sigp(float xs) {   // sigmoid, input prescaled x0.5
    return fmaf(ftanh(xs), 0.5f, 0.5f);
}

// ---------- merged prep (unchanged — known correct) ----------
__global__ void prep_all(const float* __restrict__ emb, const float* __restrict__ K,
                         const float* __restrict__ R, int nbuckets) {
    int idx = blockIdx.x * blockDim.x + threadIdx.x;
    if (idx < 4 * 16 * 32) {
        int lane = idx & 31, j = (idx >> 5) & 15, c = idx >> 9;
        int col = c * 32 + lane;
        float s = (c == 2) ? 1.0f : 0.5f;
        float lo = R[(2 * j) * 128 + col] * s;
        float hi = R[(2 * j + 1) * 128 + col] * s;
        unsigned long long v;
        asm("mov.b64 %0, {%1, %2};" : "=l"(v) : "f"(lo), "f"(hi));
        g_R[idx] = v;
    }
    int id = idx >> 5, l = idx & 31;
    if (id >= nbuckets) return;
    float a = 0.f, b = 0.f, c = 0.f, d = 0.f;
#pragma unroll
    for (int e = 0; e < 16; e++) {
        float xv = emb[id * 16 + e];
        const float* kr = K + e * 128 + l;
        a = fmaf(xv, kr[0],  a);
        b = fmaf(xv, kr[32], b);
        c = fmaf(xv, kr[64], c);
        d = fmaf(xv, kr[96], d);
    }
    *(float4*)&g_proj2[idx * 4] = make_float4(a * 0.5f, b * 0.5f, c, d * 0.5f);
}

// One gate's 16-FFMA2 dot product: two 8-deep chains, combined.
#define GATE_DOT(Z, CC, PINIT)                                                 \
    {                                                                          \
        unsigned long long Ax = pk2((PINIT), 0.f), Bx = 0ull;                  \
        fma2(Ax, RW[CC][0],  hv0.x); fma2(Bx, RW[CC][1],  hv0.y);              \
        fma2(Ax, RW[CC][2],  hv1.x); fma2(Bx, RW[CC][3],  hv1.y);              \
        fma2(Ax, RW[CC][4],  hv2.x); fma2(Bx, RW[CC][5],  hv2.y);              \
        fma2(Ax, RW[CC][6],  hv3.x); fma2(Bx, RW[CC][7],  hv3.y);              \
        fma2(Ax, RW[CC][8],  hv4.x); fma2(Bx, RW[CC][9],  hv4.y);              \
        fma2(Ax, RW[CC][10], hv5.x); fma2(Bx, RW[CC][11], hv5.y);              \
        fma2(Ax, RW[CC][12], hv6.x); fma2(Bx, RW[CC][13], hv6.y);              \
        fma2(Ax, RW[CC][14], hv7.x); fma2(Bx, RW[CC][15], hv7.y);              \
        add2(Ax, Bx);                                                          \
        float lo_, hi_;                                                        \
        unpk2(Ax, lo_, hi_);                                                   \
        Z = lo_ + hi_;                                                         \
    }

// One LSTM step: read hb[RB], write hb[WB]. Gate-major so tanh overlaps FMAs.
#define STEP_BODY(RB, WB)                                                      \
    {                                                                          \
        const ulonglong2* hp = (const ulonglong2*)&hb[RB][0];                  \
        ulonglong2 hv0 = hp[0], hv1 = hp[1], hv2 = hp[2], hv3 = hp[3];         \
        ulonglong2 hv4 = hp[4], hv5 = hp[5], hv6 = hp[6], hv7 = hp[7];         \
        float zi, zf, zc, zo;                                                  \
        GATE_DOT(zi, 0, p.x);                                                  \
        float ig = sigp(zi);                                                   \
        GATE_DOT(zf, 1, p.y);                                                  \
        float fg = sigp(zf);                                                   \
        GATE_DOT(zc, 2, p.z);                                                  \
        float gg = ftanh(zc);                                                  \
        float cn = fmaf(fg, cst, ig * gg);                                     \
        float tc = ftanh(cn);                                                  \
        GATE_DOT(zo, 3, p.w);                                                  \
        float og = sigp(zo);                                                   \
        cst = cn;                                                              \
        float h = og * tc;                                                     \
        hb[WB][lane] = h;                                                      \
        asm volatile("" ::: "memory");                                         \
    }

// ---------- main: ONE warp per CTA, gate-major inner loop, no syncwarp ----------
__global__ __launch_bounds__(32, 12) void lstm_main(
    const int* __restrict__ ids,
    const float* __restrict__ w1, const float* __restrict__ b1,
    const float* __restrict__ w2, const float* __restrict__ b2,
    float* __restrict__ out, int B)
{
    __shared__ __align__(16) float hb[2][32];      // double-buffered h
    const int lane = threadIdx.x;
    const int b = blockIdx.x;
    if (b >= B) return;

    // weights: per lane, 4 owned cols x 16 j-pairs (prescaled) = 128 regs
    unsigned long long RW[4][16];
#pragma unroll
    for (int c = 0; c < 4; c++)
#pragma unroll
        for (int j = 0; j < 16; j++)
            RW[c][j] = g_R[(c * 16 + j) * 32 + lane];

    const float4* Pp = (const float4*)g_proj2;
    const int* idrow = ids + b * T_STEPS;
    // double-buffered 32-step id blocks
    int cur = idrow[lane];
    int nxt = idrow[32 + lane];

    int id0 = __shfl_sync(0xffffffffu, cur, 0);
    float4 p = Pp[id0 * 32 + lane];                // proj for step 0 (prescaled)

    hb[0][lane] = 0.f;                             // h_0 = 0
    __syncwarp();

    float cst = 0.f;
    for (int t = 0; t < T_STEPS; t += 2) {
        // ---- even step (reads hb[0], writes hb[1]); tn = t+1 is odd -> no id refill
        {
            int idn = __shfl_sync(0xffffffffu, cur, (t + 1) & 31);
            float4 pn = Pp[idn * 32 + lane];
            STEP_BODY(0, 1);
            p = pn;
        }
        // ---- odd step (reads hb[1], writes hb[0]); tn = t+2 is even -> maybe refill
        {
            int tn = t + 2;
            int j32 = tn & 31;
            if (j32 == 0 && tn < T_STEPS) {
                cur = nxt;
                if (tn + 32 < T_STEPS) nxt = idrow[tn + 32 + lane];
            }
            int idn = __shfl_sync(0xffffffffu, cur, j32);
            float4 pn = Pp[idn * 32 + lane];
            STEP_BODY(1, 0);
            p = pn;
        }
    }

    // head: y = relu(h @ w1 + b1) @ w2 + b2  (final h in hb[0], T even)
    __syncwarp();
    float s = b1[lane];
#pragma unroll
    for (int l = 0; l < 32; l++)
        s = fmaf(hb[0][l], w1[l * 32 + lane], s);
    float r = fmaxf(s, 0.f) * w2[lane];
#pragma unroll
    for (int off = 16; off; off >>= 1)
        r += __shfl_xor_sync(0xffffffffu, r, off);
    if (lane == 0) out[b] = r + b2[0];
}

extern "C" void kernel_launch(void* const* d_in, const int* in_sizes, int n_in,
                              void* d_out, int out_size)
{
    const int*   ids  = (const int*)d_in[0];
    const float* emb  = (const float*)d_in[1];
    const float* kern = (const float*)d_in[2];
    const float* rec  = (const float*)d_in[3];
    const float* w1   = (const float*)d_in[4];
    const float* b1   = (const float*)d_in[5];
    const float* w2   = (const float*)d_in[6];
    const float* b2   = (const float*)d_in[7];

    int B = in_sizes[0] / T_STEPS;
    int nbuckets = in_sizes[1] / 16;
    if (nbuckets > 4096) nbuckets = 4096;

    int prep_threads = nbuckets * 32;
    if (prep_threads < 2048) prep_threads = 2048;
    prep_all<<<(prep_threads + 127) / 128, 128>>>(emb, kern, rec, nbuckets);
    lstm_main<<<B, 32>>>(ids, w1, b1, w2, b2, (float*)d_out, B);
}

// round 10
// speedup vs baseline: 1.1010x; 1.1010x over previous
#include <cuda_runtime.h>
#include <cstdint>

#define T_STEPS 512

// Scratch (allocation-free rule: __device__ globals)
// proj[bucket][lane] = (Pi*0.5, Pf*0.5, Pc*1.0, Po*0.5)  (0.5 = sigmoid-via-tanh prescale)
__device__ __align__(16) float g_proj2[4096 * 32 * 4];
// Rpack: ull at ((c*16 + j)*32 + lane) = (R[2j][col]*s_c, R[2j+1][col]*s_c), col = c*32+lane
__device__ __align__(16) unsigned long long g_R[4 * 16 * 32];

// ---------- packed f32x2 helpers ----------
__device__ __forceinline__ void fma2(unsigned long long& acc, unsigned long long a, unsigned long long b) {
    asm("fma.rn.f32x2 %0, %1, %2, %0;" : "+l"(acc) : "l"(a), "l"(b));
}
__device__ __forceinline__ void add2(unsigned long long& acc, unsigned long long a) {
    asm("add.rn.f32x2 %0, %0, %1;" : "+l"(acc) : "l"(a));
}
__device__ __forceinline__ unsigned long long pk2(float lo, float hi) {
    unsigned long long r;
    asm("mov.b64 %0, {%1, %2};" : "=l"(r) : "f"(lo), "f"(hi));
    return r;
}
__device__ __forceinline__ void unpk2(unsigned long long v, float& lo, float& hi) {
    asm("mov.b64 {%0, %1}, %2;" : "=f"(lo), "=f"(hi) : "l"(v));
}
__device__ __forceinline__ float ftanh(float x) {
    float y; asm("tanh.approx.f32 %0, %1;" : "=f"(y) : "f"(x)); return y;
}
__device__ __forceinline__ float sigp(float xs) {   // sigmoid, input prescaled x0.5
    return fmaf(ftanh(xs), 0.5f, 0.5f);
}

// ---------- merged prep (unchanged — known correct) ----------
__global__ void prep_all(const float* __restrict__ emb, const float* __restrict__ K,
                         const float* __restrict__ R, int nbuckets) {
    int idx = blockIdx.x * blockDim.x + threadIdx.x;
    if (idx < 4 * 16 * 32) {
        int lane = idx & 31, j = (idx >> 5) & 15, c = idx >> 9;
        int col = c * 32 + lane;
        float s = (c == 2) ? 1.0f : 0.5f;
        float lo = R[(2 * j) * 128 + col] * s;
        float hi = R[(2 * j + 1) * 128 + col] * s;
        unsigned long long v;
        asm("mov.b64 %0, {%1, %2};" : "=l"(v) : "f"(lo), "f"(hi));
        g_R[idx] = v;
    }
    int id = idx >> 5, l = idx & 31;
    if (id >= nbuckets) return;
    float a = 0.f, b = 0.f, c = 0.f, d = 0.f;
#pragma unroll
    for (int e = 0; e < 16; e++) {
        float xv = emb[id * 16 + e];
        const float* kr = K + e * 128 + l;
        a = fmaf(xv, kr[0],  a);
        b = fmaf(xv, kr[32], b);
        c = fmaf(xv, kr[64], c);
        d = fmaf(xv, kr[96], d);
    }
    *(float4*)&g_proj2[idx * 4] = make_float4(a * 0.5f, b * 0.5f, c, d * 0.5f);
}

// One LSTM step: read hb[RB], write hb[WB].
// Phase 1: gates i,f,c (h consumed transiently). Phase 2: o-gate FMAs (h reloaded
// from smem) overlap the i/f/c tanh + cell-state chain.
#define STEP_BODY(RB, WB)                                                      \
    {                                                                          \
        const ulonglong2* hp = (const ulonglong2*)&hb[RB][0];                  \
        unsigned long long aI = pk2(p.x, 0.f);                                 \
        unsigned long long aF = pk2(p.y, 0.f);                                 \
        unsigned long long aC = pk2(p.z, 0.f);                                 \
        _Pragma("unroll")                                                      \
        for (int k = 0; k < 8; k++) {                                          \
            ulonglong2 hv = hp[k];          /* broadcast LDS.128, transient */ \
            fma2(aI, RW[0][2 * k], hv.x);                                      \
            fma2(aF, RW[1][2 * k], hv.x);                                      \
            fma2(aC, RW[2][2 * k], hv.x);                                      \
            fma2(aI, RW[0][2 * k + 1], hv.y);                                  \
            fma2(aF, RW[1][2 * k + 1], hv.y);                                  \
            fma2(aC, RW[2][2 * k + 1], hv.y);                                  \
        }                                                                      \
        float lo_, hi_;                                                        \
        unpk2(aI, lo_, hi_); float zi = lo_ + hi_;                             \
        unpk2(aF, lo_, hi_); float zf = lo_ + hi_;                             \
        unpk2(aC, lo_, hi_); float zc = lo_ + hi_;                             \
        float ig = sigp(zi);                                                   \
        float fg = sigp(zf);                                                   \
        float gg = ftanh(zc);                                                  \
        /* o-gate: reload h (cheap broadcast LDS) while the chain above runs */\
        unsigned long long aO0 = pk2(p.w, 0.f), aO1 = 0ull;                    \
        _Pragma("unroll")                                                      \
        for (int k = 0; k < 8; k++) {                                          \
            ulonglong2 hv = hp[k];                                             \
            fma2(aO0, RW[3][2 * k], hv.x);                                     \
            fma2(aO1, RW[3][2 * k + 1], hv.y);                                 \
        }                                                                      \
        float cn = fmaf(fg, cst, ig * gg);                                     \
        float tc = ftanh(cn);                                                  \
        add2(aO0, aO1);                                                        \
        unpk2(aO0, lo_, hi_); float zo = lo_ + hi_;                            \
        float og = sigp(zo);                                                   \
        cst = cn;                                                              \
        hb[WB][lane] = og * tc;                                                \
        asm volatile("" ::: "memory");                                         \
    }

// ---------- main: ONE warp per CTA, overlap-tail inner loop, no syncwarp ----------
__global__ __launch_bounds__(32, 12) void lstm_main(
    const int* __restrict__ ids,
    const float* __restrict__ w1, const float* __restrict__ b1,
    const float* __restrict__ w2, const float* __restrict__ b2,
    float* __restrict__ out, int B)
{
    __shared__ __align__(16) float hb[2][32];      // double-buffered h
    const int lane = threadIdx.x;
    const int b = blockIdx.x;
    if (b >= B) return;

    // weights: per lane, 4 gate-cols x 16 j-pairs (prescaled) = 128 regs
    unsigned long long RW[4][16];
#pragma unroll
    for (int c = 0; c < 4; c++)
#pragma unroll
        for (int j = 0; j < 16; j++)
            RW[c][j] = g_R[(c * 16 + j) * 32 + lane];

    const float4* Pp = (const float4*)g_proj2;
    const int* idrow = ids + b * T_STEPS;
    // double-buffered 32-step id blocks
    int cur = idrow[lane];
    int nxt = idrow[32 + lane];

    int id0 = __shfl_sync(0xffffffffu, cur, 0);
    float4 p = Pp[id0 * 32 + lane];                // proj for step 0 (prescaled)

    hb[0][lane] = 0.f;                             // h_0 = 0
    __syncwarp();

    float cst = 0.f;
    for (int t = 0; t < T_STEPS; t += 2) {
        // ---- even step (reads hb[0], writes hb[1]); tn = t+1 odd -> no id refill
        {
            int idn = __shfl_sync(0xffffffffu, cur, (t + 1) & 31);
            float4 pn = Pp[idn * 32 + lane];
            STEP_BODY(0, 1);
            p = pn;
        }
        // ---- odd step (reads hb[1], writes hb[0]); tn = t+2 even -> maybe refill
        {
            int tn = t + 2;
            int j32 = tn & 31;
            if (j32 == 0 && tn < T_STEPS) {
                cur = nxt;
                if (tn + 32 < T_STEPS) nxt = idrow[tn + 32 + lane];
            }
            int idn = __shfl_sync(0xffffffffu, cur, j32);
            float4 pn = Pp[idn * 32 + lane];
            STEP_BODY(1, 0);
            p = pn;
        }
    }

    // head: y = relu(h @ w1 + b1) @ w2 + b2  (final h in hb[0], T even)
    __syncwarp();
    float s = b1[lane];
#pragma unroll
    for (int l = 0; l < 32; l++)
        s = fmaf(hb[0][l], w1[l * 32 + lane], s);
    float r = fmaxf(s, 0.f) * w2[lane];
#pragma unroll
    for (int off = 16; off; off >>= 1)
        r += __shfl_xor_sync(0xffffffffu, r, off);
    if (lane == 0) out[b] = r + b2[0];
}

extern "C" void kernel_launch(void* const* d_in, const int* in_sizes, int n_in,
                              void* d_out, int out_size)
{
    const int*   ids  = (const int*)d_in[0];
    const float* emb  = (const float*)d_in[1];
    const float* kern = (const float*)d_in[2];
    const float* rec  = (const float*)d_in[3];
    const float* w1   = (const float*)d_in[4];
    const float* b1   = (const float*)d_in[5];
    const float* w2   = (const float*)d_in[6];
    const float* b2   = (const float*)d_in[7];

    int B = in_sizes[0] / T_STEPS;
    int nbuckets = in_sizes[1] / 16;
    if (nbuckets > 4096) nbuckets = 4096;

    int prep_threads = nbuckets * 32;
    if (prep_threads < 2048) prep_threads = 2048;
    prep_all<<<(prep_threads + 127) / 128, 128>>>(emb, kern, rec, nbuckets);
    lstm_main<<<B, 32>>>(ids, w1, b1, w2, b2, (float*)d_out, B);
}

// round 11
// speedup vs baseline: 1.2084x; 1.0975x over previous
#include <cuda_runtime.h>
#include <cstdint>

#define T_STEPS 512

// Scratch (allocation-free rule: __device__ globals)
// proj[bucket][lane] = (Pi*0.5, Pf*0.5, Pc*1.0, Po*0.5)  (0.5 = sigmoid-via-tanh prescale)
__device__ __align__(16) float g_proj2[4096 * 32 * 4];
// Rpack: ull at ((c*16 + j)*32 + lane) = (R[2j][col]*s_c, R[2j+1][col]*s_c), col = c*32+lane
__device__ __align__(16) unsigned long long g_R[4 * 16 * 32];

// ---------- packed f32x2 helpers ----------
__device__ __forceinline__ void fma2(unsigned long long& acc, unsigned long long a, unsigned long long b) {
    asm("fma.rn.f32x2 %0, %1, %2, %0;" : "+l"(acc) : "l"(a), "l"(b));
}
__device__ __forceinline__ unsigned long long pk2(float lo, float hi) {
    unsigned long long r;
    asm("mov.b64 %0, {%1, %2};" : "=l"(r) : "f"(lo), "f"(hi));
    return r;
}
__device__ __forceinline__ void unpk2(unsigned long long v, float& lo, float& hi) {
    asm("mov.b64 {%0, %1}, %2;" : "=f"(lo), "=f"(hi) : "l"(v));
}
__device__ __forceinline__ float ftanh(float x) {
    float y; asm("tanh.approx.f32 %0, %1;" : "=f"(y) : "f"(x)); return y;
}
__device__ __forceinline__ float sigp(float xs) {   // sigmoid, input prescaled x0.5
    return fmaf(ftanh(xs), 0.5f, 0.5f);
}

// ---------- merged prep (unchanged — known correct) ----------
__global__ void prep_all(const float* __restrict__ emb, const float* __restrict__ K,
                         const float* __restrict__ R, int nbuckets) {
    int idx = blockIdx.x * blockDim.x + threadIdx.x;
    if (idx < 4 * 16 * 32) {
        int lane = idx & 31, j = (idx >> 5) & 15, c = idx >> 9;
        int col = c * 32 + lane;
        float s = (c == 2) ? 1.0f : 0.5f;
        float lo = R[(2 * j) * 128 + col] * s;
        float hi = R[(2 * j + 1) * 128 + col] * s;
        unsigned long long v;
        asm("mov.b64 %0, {%1, %2};" : "=l"(v) : "f"(lo), "f"(hi));
        g_R[idx] = v;
    }
    int id = idx >> 5, l = idx & 31;
    if (id >= nbuckets) return;
    float a = 0.f, b = 0.f, c = 0.f, d = 0.f;
#pragma unroll
    for (int e = 0; e < 16; e++) {
        float xv = emb[id * 16 + e];
        const float* kr = K + e * 128 + l;
        a = fmaf(xv, kr[0],  a);
        b = fmaf(xv, kr[32], b);
        c = fmaf(xv, kr[64], c);
        d = fmaf(xv, kr[96], d);
    }
    *(float4*)&g_proj2[idx * 4] = make_float4(a * 0.5f, b * 0.5f, c, d * 0.5f);
}

// ---------- main: ONE warp per CTA, R8 inner loop + phase-stagger prologue ----------
__global__ __launch_bounds__(32, 12) void lstm_main(
    const int* __restrict__ ids,
    const float* __restrict__ w1, const float* __restrict__ b1,
    const float* __restrict__ w2, const float* __restrict__ b2,
    float* __restrict__ out, int B)
{
    __shared__ __align__(16) float hb[2][32];      // double-buffered h
    const int lane = threadIdx.x & 31;
    const int b = blockIdx.x;
    if (b >= B) return;

    // ---- de-convoy stagger: co-resident CTAs (bid differing by ~148) get
    // phase offsets of 0/64/128/192 cyc via a dependent-FMA spin.
    // Deterministic; result provably never escapes (stays ~1e-27).
    {
        int phase = (blockIdx.x / 148) & 3;
        float dummy = 1e-30f;
#pragma unroll 1
        for (int i = 0; i < phase * 16; i++)
            dummy = fmaf(dummy, 0.999f, 1e-30f);
        if (dummy > 1e10f) hb[0][0] = dummy;   // never true
    }

    // weights: per lane, 4 owned cols x 16 j-pairs (prescaled) = 128 regs
    unsigned long long RW[4][16];
#pragma unroll
    for (int c = 0; c < 4; c++)
#pragma unroll
        for (int j = 0; j < 16; j++)
            RW[c][j] = g_R[(c * 16 + j) * 32 + lane];

    const float4* Pp = (const float4*)g_proj2;
    const int* idrow = ids + b * T_STEPS;
    // double-buffered 32-step id blocks (no load-to-use stall at block boundary)
    int cur = idrow[lane];
    int nxt = idrow[32 + lane];

    int id0 = __shfl_sync(0xffffffffu, cur, 0);
    float4 p = Pp[id0 * 32 + lane];                // proj for step 0 (prescaled)

    hb[0][lane] = 0.f;                             // h_0 = 0
    __syncwarp();

    float cst = 0.f;
    for (int t = 0; t < T_STEPS; t++) {
        // prefetch proj for step t+1 (hidden behind this step's math)
        int tn = t + 1;
        int j32 = tn & 31;
        if (j32 == 0 && tn < T_STEPS) {
            cur = nxt;
            if (tn + 32 < T_STEPS) nxt = idrow[tn + 32 + lane];
        }
        int idn = __shfl_sync(0xffffffffu, cur, j32);
        float4 pn = Pp[idn * 32 + lane];

        // proj folded into acc init (even half) — saves tail FADDs
        unsigned long long a0 = pk2(p.x, 0.f);
        unsigned long long a1 = pk2(p.y, 0.f);
        unsigned long long a2 = pk2(p.z, 0.f);
        unsigned long long a3 = pk2(p.w, 0.f);
        const ulonglong2* hp = (const ulonglong2*)&hb[t & 1][0];
#pragma unroll
        for (int k = 0; k < 8; k++) {
            ulonglong2 hv = hp[k];              // (h4k,h4k+1),(h4k+2,h4k+3) broadcast LDS.128
            fma2(a0, RW[0][2 * k], hv.x);
            fma2(a1, RW[1][2 * k], hv.x);
            fma2(a2, RW[2][2 * k], hv.x);
            fma2(a3, RW[3][2 * k], hv.x);
            fma2(a0, RW[0][2 * k + 1], hv.y);
            fma2(a1, RW[1][2 * k + 1], hv.y);
            fma2(a2, RW[2][2 * k + 1], hv.y);
            fma2(a3, RW[3][2 * k + 1], hv.y);
        }
        float lo, hi;
        unpk2(a0, lo, hi); float zi = lo + hi;
        unpk2(a1, lo, hi); float zf = lo + hi;
        unpk2(a2, lo, hi); float zc = lo + hi;
        unpk2(a3, lo, hi); float zo = lo + hi;

        float ig = sigp(zi);
        float fg = sigp(zf);
        float og = sigp(zo);
        float gg = ftanh(zc);
        cst = fmaf(fg, cst, ig * gg);
        float h = og * ftanh(cst);

        hb[tn & 1][lane] = h;
        __syncwarp();
        p = pn;
    }

    // head: y = relu(h @ w1 + b1) @ w2 + b2  (final h in hb[0], T even)
    float s = b1[lane];
#pragma unroll
    for (int l = 0; l < 32; l++)
        s = fmaf(hb[0][l], w1[l * 32 + lane], s);
    float r = fmaxf(s, 0.f) * w2[lane];
#pragma unroll
    for (int off = 16; off; off >>= 1)
        r += __shfl_xor_sync(0xffffffffu, r, off);
    if (lane == 0) out[b] = r + b2[0];
}

extern "C" void kernel_launch(void* const* d_in, const int* in_sizes, int n_in,
                              void* d_out, int out_size)
{
    const int*   ids  = (const int*)d_in[0];
    const float* emb  = (const float*)d_in[1];
    const float* kern = (const float*)d_in[2];
    const float* rec  = (const float*)d_in[3];
    const float* w1   = (const float*)d_in[4];
    const float* b1   = (const float*)d_in[5];
    const float* w2   = (const float*)d_in[6];
    const float* b2   = (const float*)d_in[7];

    int B = in_sizes[0] / T_STEPS;
    int nbuckets = in_sizes[1] / 16;
    if (nbuckets > 4096) nbuckets = 4096;

    int prep_threads = nbuckets * 32;
    if (prep_threads < 2048) prep_threads = 2048;
    prep_all<<<(prep_threads + 127) / 128, 128>>>(emb, kern, rec, nbuckets);
    lstm_main<<<B, 32>>>(ids, w1, b1, w2, b2, (float*)d_out, B);
}